// round 16
// baseline (speedup 1.0000x reference)
#include <cuda_runtime.h>

#define BB 8
#define NNROWS 4000
#define CC 80
#define NC (NNROWS*CC)        // 320000
#define KPRE 2048
#define DETN 100
#define NWORDS (KPRE/64)      // 32
#define CAPS 6144
#define CLIPF 4.135166556742356f
#define INVBIN 0x407Fu        // f2ord(-1.0f) >> 16

typedef unsigned long long ull;

// ---------------- device scratch (static, no allocation) ----------------
__device__ unsigned int g_ord[BB][NC];        // 10.25 MB
__device__ unsigned int g_hist16[BB][65536];  // 2 MB (zero-init at load; re-zeroed by k_mega)

// ---------------- helpers ----------------
__device__ __forceinline__ unsigned f2ord(float f) {
    unsigned u = __float_as_uint(f);
    return (u & 0x80000000u) ? ~u : (u | 0x80000000u);
}
__device__ __forceinline__ float ord2f(unsigned o) {
    unsigned u = (o & 0x80000000u) ? (o ^ 0x80000000u) : ~o;
    return __uint_as_float(u);
}

__device__ __forceinline__ void decode_box(float d0, float d1, float d2, float d3,
                                           float4 p,
                                           float& x1, float& y1, float& x2, float& y2) {
    float w  = p.z - p.x;
    float h  = p.w - p.y;
    float cx = p.x + 0.5f * w;
    float cy = p.y + 0.5f * h;
    float dx = d0 / 10.0f;
    float dy = d1 / 10.0f;
    float dw = fminf(d2 / 5.0f, CLIPF);
    float dh = fminf(d3 / 5.0f, CLIPF);
    float pcx = dx * w + cx;
    float pcy = dy * h + cy;
    float pw  = expf(dw) * w;
    float ph  = expf(dh) * h;
    x1 = pcx - 0.5f * pw;
    y1 = pcy - 0.5f * ph;
    x2 = pcx + 0.5f * pw;
    y2 = pcy + 0.5f * ph;
}

// block-wide digit select over 256 counts: find largest d such that
// sum(cnt[d..255]) >= k; out_acc = count strictly above d. All 1024 threads enter.
__device__ __forceinline__ void sel_digit(const unsigned* cnt, unsigned k,
                                          unsigned* scan, int* out_dig, unsigned* out_acc,
                                          int tid) {
    if (tid < 256) scan[tid] = cnt[255 - tid];
    __syncthreads();
#pragma unroll
    for (int off = 1; off < 256; off <<= 1) {
        unsigned v = 0;
        if (tid < 256 && tid >= off) v = scan[tid - off];
        __syncthreads();
        if (tid < 256) scan[tid] += v;
        __syncthreads();
    }
    if (tid < 256) {
        bool hit = (scan[tid] >= k) && (tid == 0 || scan[tid - 1] < k);
        if (hit) { *out_dig = 255 - tid; *out_acc = scan[tid] - cnt[255 - tid]; }
    }
    __syncthreads();
}

// ---------------- scorekey: softmax + validity + 32-bit ord + 16-bit hist ----
__global__ __launch_bounds__(256) void k_scorekey(const float* __restrict__ label,
                                                  const float* __restrict__ bbox,
                                                  const float* __restrict__ props) {
    int img  = blockIdx.y;
    int warp = threadIdx.x >> 5;
    int lane = threadIdx.x & 31;
    int row  = blockIdx.x * 8 + warp;
    if (row >= NNROWS) return;

    const float* L = label + ((size_t)img * NNROWS + row) * (CC + 1);

    float l0 = L[lane];
    float l1 = L[lane + 32];
    float l2 = (lane < 17) ? L[lane + 64] : -3.402823466e38f;

    float m = fmaxf(fmaxf(l0, l1), l2);
#pragma unroll
    for (int o = 16; o > 0; o >>= 1) m = fmaxf(m, __shfl_xor_sync(0xffffffffu, m, o));

    float e0 = __expf(l0 - m);
    float e1 = __expf(l1 - m);
    float e2 = (lane < 17) ? __expf(l2 - m) : 0.0f;

    float ssum = e0 + e1 + e2;
#pragma unroll
    for (int o = 16; o > 0; o >>= 1) ssum += __shfl_xor_sync(0xffffffffu, ssum, o);
    float inv = 1.0f / ssum;

    int src = (lane + 1) & 31;
    float a  = __shfl_sync(0xffffffffu, e0, src);
    float b  = __shfl_sync(0xffffffffu, e1, src);
    float cv = __shfl_sync(0xffffffffu, e2, src);
    float sc0 = ((lane < 31) ? a : b) * inv;    // class lane+1
    float sc1 = ((lane < 31) ? b : cv) * inv;   // class lane+33
    float sc2 = cv * inv;                        // class lane+65 (lane<16)

    float4 p = ((const float4*)props)[img * NNROWS + row];
    float w  = p.z - p.x;
    float h  = p.w - p.y;
    float wh = w * h;
    const float4* D4 = (const float4*)(bbox + ((size_t)img * NNROWS + row) * ((CC + 1) * 4) + 4);
    unsigned* O = &g_ord[img][row * CC];

    int invc = 0;
#pragma unroll
    for (int k = 0; k < 3; k++) {
        int c = lane + 32 * k;
        if (c >= CC) break;
        float sc = (k == 0) ? sc0 : (k == 1) ? sc1 : sc2;
        bool valid = false;
        if (sc > 0.01f) {
            float4 d = D4[c];
            float dw = fminf(d.z / 5.0f, CLIPF);
            float dh = fminf(d.w / 5.0f, CLIPF);
            float area = __expf(dw + dh) * wh;
            valid = (area > 0.1f);
        }
        unsigned ordv;
        if (valid) {
            ordv = f2ord(sc);
            atomicAdd(&g_hist16[img][ordv >> 16], 1u);
        } else {
            ordv = (INVBIN << 16) | 0xFFFFu;   // f2ord(-1.0f)
            invc++;
        }
        O[c] = ordv;
    }
#pragma unroll
    for (int o = 16; o > 0; o >>= 1) invc += __shfl_xor_sync(0xffffffffu, invc, o);
    if (lane == 0 && invc) atomicAdd(&g_hist16[img][INVBIN], (unsigned)invc);
}

// ---------------- mega: select16 + compact + refine + sort + decode + NMS + out
__global__ __launch_bounds__(1024) void k_mega(const float* __restrict__ bbox,
                                               const float* __restrict__ props,
                                               float* __restrict__ out) {
    int img = blockIdx.x;
    int tid = threadIdx.x;
    int wid = tid >> 5;
    int lane = tid & 31;

    extern __shared__ ull dyn[];
    ull*    s_top    = dyn;                         // 2048 (complemented keys)
    ull*    s_cand   = dyn + KPRE;                  // CAPS
    float4* s_nmsb   = (float4*)(s_cand + CAPS);    // 2048
    float4* s_boxes  = s_nmsb + KPRE;               // 2048
    float*  s_scores = (float*)(s_boxes + KPRE);    // 2048
    int*    s_labels = (int*)(s_scores + KPRE);     // 2048

    __shared__ unsigned csum[256];
    __shared__ unsigned sb[256];
    __shared__ unsigned scan[256];
    __shared__ unsigned rhist[256];
    __shared__ int  s_dig;
    __shared__ unsigned s_acc;
    __shared__ unsigned s_prefix;
    __shared__ int s_cntA, s_cntC, s_cnt2, s_V, s_k2, snk;
    __shared__ ull s_pfx;
    __shared__ float4 kb[DETN];
    __shared__ int ki[DETN];
    __shared__ ull keepm[NWORDS];
    __shared__ int sdet[DETN];
    __shared__ int sflag[DETN];

    if (tid == 0) { s_cntA = 0; s_cntC = 0; s_cnt2 = 0; }

    // ---- phase 1: 16-bit bucket select ----
    for (int c = wid; c < 256; c += 32) {
        const unsigned* h = &g_hist16[img][c * 256];
        unsigned s = 0;
#pragma unroll
        for (int k = 0; k < 8; k++) s += h[lane + 32 * k];
#pragma unroll
        for (int o = 16; o > 0; o >>= 1) s += __shfl_xor_sync(0xffffffffu, s, o);
        if (lane == 0) csum[c] = s;
    }
    __syncthreads();
    sel_digit(csum, KPRE, scan, &s_dig, &s_acc, tid);
    int tc = s_dig;
    unsigned acc1 = s_acc;
    if (tid < 256) sb[tid] = g_hist16[img][tc * 256 + tid];
    __syncthreads();
    sel_digit(sb, KPRE - acc1, scan, &s_dig, &s_acc, tid);
    if (tid == 0) s_prefix = (unsigned)(tc * 256 + s_dig);
    __syncthreads();
    unsigned prefix = s_prefix;

    // re-zero this image's hist slice for the next replay (idempotent graph)
    {
        uint4* hz = (uint4*)g_hist16[img];
#pragma unroll
        for (int k = 0; k < 16; k++) hz[tid + 1024 * k] = make_uint4(0u, 0u, 0u, 0u);
    }

    // ---- phase 2: compact (>bucket -> s_top complemented, ==bucket -> s_cand) ----
    {
        const uint4* src = (const uint4*)g_ord[img];
        const int n4 = NC / 4;                    // 80000
        for (int it = 0; it < 79; it++) {
            int i = it * 1024 + tid;
            uint4 v = make_uint4(0u, 0u, 0u, 0u);
            if (i < n4) v = src[i];
#pragma unroll
            for (int e = 0; e < 4; e++) {
                unsigned ordv = (e == 0) ? v.x : (e == 1) ? v.y : (e == 2) ? v.z : v.w;
                unsigned p16 = ordv >> 16;
                bool ab = (p16 > prefix);
                bool eq = (p16 == prefix);
                unsigned balA = __ballot_sync(0xffffffffu, ab);
                unsigned balE = __ballot_sync(0xffffffffu, eq);
                int baseA = 0, baseE = 0;
                if (lane == 0) {
                    if (balA) baseA = atomicAdd(&s_cntA, __popc(balA));
                    if (balE) baseE = atomicAdd(&s_cntC, __popc(balE));
                }
                baseA = __shfl_sync(0xffffffffu, baseA, 0);
                baseE = __shfl_sync(0xffffffffu, baseE, 0);
                unsigned lm = (1u << lane) - 1u;
                unsigned idx = (unsigned)(i * 4 + e);
                ull key = ((ull)ordv << 32) | (ull)(0xFFFFFFFFu - idx);
                if (ab) {
                    s_top[baseA + __popc(balA & lm)] = ~key;
                } else if (eq) {
                    int p = baseE + __popc(balE & lm);
                    if (p < CAPS) s_cand[p] = key;
                }
            }
        }
    }
    __syncthreads();

    // ---- phase 3: exact 64-bit refine within pivot bucket ----
    int n = s_cntC; if (n > CAPS) n = CAPS;
    int above = s_cntA;
    if (tid == 0) { s_pfx = (ull)prefix << 48; s_k2 = KPRE - above; }
    __syncthreads();

    for (int r = 0; r < 6; r++) {
        int sh = 40 - 8 * r;
        if (tid < 256) rhist[tid] = 0;
        __syncthreads();
        ull hi_mask = ~((1ull << (sh + 8)) - 1ull);
        ull pfx = s_pfx;
        for (int i = tid; i < n; i += 1024) {
            ull key = s_cand[i];
            if ((key & hi_mask) == pfx)
                atomicAdd(&rhist[(unsigned)(key >> sh) & 0xFFu], 1u);
        }
        __syncthreads();
        sel_digit(rhist, (unsigned)s_k2, scan, &s_dig, &s_acc, tid);
        if (tid == 0) {
            s_pfx |= ((ull)s_dig) << sh;
            s_k2 -= (int)s_acc;
        }
        __syncthreads();
    }
    {
        ull pivot = s_pfx;
        for (int i = tid; i < n; i += 1024) {
            ull key = s_cand[i];
            if (key >= pivot) {
                int p = above + atomicAdd(&s_cnt2, 1);
                s_top[p] = ~key;
            }
        }
    }
    __syncthreads();

    // ---- phase 4: bitonic sort 2048 complemented keys ascending (= real desc) ----
    for (int ksz = 2; ksz <= KPRE; ksz <<= 1) {
        for (int j = ksz >> 1; j > 0; j >>= 1) {
            for (int i = tid; i < KPRE; i += 1024) {
                int ixj = i ^ j;
                if (ixj > i) {
                    ull a = s_top[i], b = s_top[ixj];
                    bool up = ((i & ksz) == 0);
                    if ((a > b) == up) { s_top[i] = b; s_top[ixj] = a; }
                }
            }
            __syncthreads();
        }
    }

    // ---- phase 5: decode top 2048 (precise expf) ----
    for (int i = tid; i < KPRE; i += 1024) {
        ull key = ~s_top[i];
        float sc = ord2f((unsigned)(key >> 32));
        unsigned idx = 0xFFFFFFFFu - (unsigned)(key & 0xFFFFFFFFull);
        int nr = (int)(idx / CC);
        int c  = (int)(idx - (unsigned)nr * CC);
        float4 p = ((const float4*)props)[img * NNROWS + nr];
        const float4* D4 = (const float4*)(bbox + ((size_t)img * NNROWS + nr) * ((CC + 1) * 4) + 4);
        float4 d = D4[c];
        float x1, y1, x2, y2;
        decode_box(d.x, d.y, d.z, d.w, p, x1, y1, x2, y2);
        s_scores[i] = sc;
        s_boxes[i]  = make_float4(x1, y1, x2, y2);
        float off = (float)(c + 1) * 4096.0f;
        s_nmsb[i]   = make_float4(x1 + off, y1 + off, x2 + off, y2 + off);
        s_labels[i] = c + 1;

        if (i == 0 && !(sc > 0.0f)) s_V = 0;
        if (sc > 0.0f) {
            if (i == KPRE - 1) s_V = KPRE;
            else {
                float nx = ord2f((unsigned)((~s_top[i + 1]) >> 32));
                if (!(nx > 0.0f)) s_V = i + 1;
            }
        }
    }
    __syncthreads();

    // ---- phase 6: lazy greedy NMS (warp 0), early exit at DETN keeps ----
    if (tid < 32) {
        if (lane < NWORDS) keepm[lane] = 0ull;
        int V = s_V;
        __syncwarp();
        int nk = 0;
        for (int i = 0; i < V && nk < DETN; i++) {
            float4 a = s_nmsb[i];
            float aw = fmaxf(a.z - a.x, 0.0f), ah = fmaxf(a.w - a.y, 0.0f);
            float areaA = aw * ah;
            bool sup = false;
            for (int j = lane; j < nk; j += 32) {
                float4 b = kb[j];
                float bw = fmaxf(b.z - b.x, 0.0f), bh = fmaxf(b.w - b.y, 0.0f);
                float w = fmaxf(fminf(a.z, b.z) - fmaxf(a.x, b.x), 0.0f);
                float h = fmaxf(fminf(a.w, b.w) - fmaxf(a.y, b.y), 0.0f);
                float inter = w * h;
                float uni = areaA + bw * bh - inter;
                if (inter / fmaxf(uni, 1e-9f) > 0.5f) sup = true;
            }
            if (!__any_sync(0xffffffffu, sup)) {
                if (lane == 0) {
                    kb[nk] = a;
                    ki[nk] = i;
                    keepm[i >> 6] |= (1ull << (i & 63));
                }
                __syncwarp();
                nk++;
            }
        }
        if (lane == 0) snk = nk;
    }
    __syncthreads();

    if (tid == 0) {
        int c = 0, nk = snk;
        for (int q = 0; q < nk; q++) { sdet[c] = ki[q]; sflag[c] = 1; c++; }
        for (int i = 0; i < KPRE && c < DETN; i++)
            if (!((keepm[i >> 6] >> (i & 63)) & 1ull)) { sdet[c] = i; sflag[c] = 0; c++; }
    }
    __syncthreads();

    if (tid < DETN) {
        int i = sdet[tid];
        float4 b = s_boxes[i];
        int o = img * DETN + tid;
        out[o * 4 + 0] = b.x;
        out[o * 4 + 1] = b.y;
        out[o * 4 + 2] = b.z;
        out[o * 4 + 3] = b.w;
        out[BB * DETN * 4 + o] = sflag[tid] ? s_scores[i] : -1.0f;
        out[BB * DETN * 5 + o] = (float)s_labels[i];
    }
}

// ---------------- launch ----------------
extern "C" void kernel_launch(void* const* d_in, const int* in_sizes, int n_in,
                              void* d_out, int out_size) {
    const float* label = (const float*)d_in[0];
    const float* bbox  = (const float*)d_in[1];
    const float* props = (const float*)d_in[2];
    float* out = (float*)d_out;

    const int MEGA_SMEM = (KPRE + CAPS) * 8 + KPRE * 16 * 2 + KPRE * 4 * 2; // 147456
    cudaFuncSetAttribute(k_mega, cudaFuncAttributeMaxDynamicSharedMemorySize, MEGA_SMEM);

    k_scorekey<<<dim3(500, BB), 256>>>(label, bbox, props);
    k_mega<<<BB, 1024, MEGA_SMEM>>>(bbox, props, out);
}

// round 17
// speedup vs baseline: 1.0008x; 1.0008x over previous
#include <cuda_runtime.h>

#define BB 8
#define NNROWS 4000
#define CC 80
#define NC (NNROWS*CC)        // 320000
#define KPRE 2048
#define DETN 100
#define NWORDS (KPRE/64)      // 32
#define CAPS 6144
#define CLIPF 4.135166556742356f
#define INVBIN 0x407Fu        // f2ord(-1.0f) >> 16

typedef unsigned long long ull;

// ---------------- device scratch (static, no allocation) ----------------
__device__ unsigned int g_ord[BB][NC];        // 10.25 MB
__device__ unsigned int g_hist16[BB][65536];  // 2 MB (zero-init at load; re-zeroed by k_mega)

// ---------------- helpers ----------------
__device__ __forceinline__ unsigned f2ord(float f) {
    unsigned u = __float_as_uint(f);
    return (u & 0x80000000u) ? ~u : (u | 0x80000000u);
}
__device__ __forceinline__ float ord2f(unsigned o) {
    unsigned u = (o & 0x80000000u) ? (o ^ 0x80000000u) : ~o;
    return __uint_as_float(u);
}

__device__ __forceinline__ void decode_box(float d0, float d1, float d2, float d3,
                                           float4 p,
                                           float& x1, float& y1, float& x2, float& y2) {
    float w  = p.z - p.x;
    float h  = p.w - p.y;
    float cx = p.x + 0.5f * w;
    float cy = p.y + 0.5f * h;
    float dx = d0 / 10.0f;
    float dy = d1 / 10.0f;
    float dw = fminf(d2 / 5.0f, CLIPF);
    float dh = fminf(d3 / 5.0f, CLIPF);
    float pcx = dx * w + cx;
    float pcy = dy * h + cy;
    float pw  = expf(dw) * w;
    float ph  = expf(dh) * h;
    x1 = pcx - 0.5f * pw;
    y1 = pcy - 0.5f * ph;
    x2 = pcx + 0.5f * pw;
    y2 = pcy + 0.5f * ph;
}

// block-wide digit select over 256 counts: find largest d such that
// sum(cnt[d..255]) >= k; out_acc = count strictly above d. All 1024 threads enter.
__device__ __forceinline__ void sel_digit(const unsigned* cnt, unsigned k,
                                          unsigned* scan, int* out_dig, unsigned* out_acc,
                                          int tid) {
    if (tid < 256) scan[tid] = cnt[255 - tid];
    __syncthreads();
#pragma unroll
    for (int off = 1; off < 256; off <<= 1) {
        unsigned v = 0;
        if (tid < 256 && tid >= off) v = scan[tid - off];
        __syncthreads();
        if (tid < 256) scan[tid] += v;
        __syncthreads();
    }
    if (tid < 256) {
        bool hit = (scan[tid] >= k) && (tid == 0 || scan[tid - 1] < k);
        if (hit) { *out_dig = 255 - tid; *out_acc = scan[tid] - cnt[255 - tid]; }
    }
    __syncthreads();
}

// ---------------- scorekey: softmax + validity + 32-bit ord + 16-bit hist ----
__global__ __launch_bounds__(256) void k_scorekey(const float* __restrict__ label,
                                                  const float* __restrict__ bbox,
                                                  const float* __restrict__ props) {
    int img  = blockIdx.y;
    int warp = threadIdx.x >> 5;
    int lane = threadIdx.x & 31;
    int row  = blockIdx.x * 8 + warp;
    if (row >= NNROWS) return;

    const float* L = label + ((size_t)img * NNROWS + row) * (CC + 1);

    float l0 = L[lane];
    float l1 = L[lane + 32];
    float l2 = (lane < 17) ? L[lane + 64] : -3.402823466e38f;

    float m = fmaxf(fmaxf(l0, l1), l2);
#pragma unroll
    for (int o = 16; o > 0; o >>= 1) m = fmaxf(m, __shfl_xor_sync(0xffffffffu, m, o));

    float e0 = __expf(l0 - m);
    float e1 = __expf(l1 - m);
    float e2 = (lane < 17) ? __expf(l2 - m) : 0.0f;

    float ssum = e0 + e1 + e2;
#pragma unroll
    for (int o = 16; o > 0; o >>= 1) ssum += __shfl_xor_sync(0xffffffffu, ssum, o);
    float inv = 1.0f / ssum;

    int src = (lane + 1) & 31;
    float a  = __shfl_sync(0xffffffffu, e0, src);
    float b  = __shfl_sync(0xffffffffu, e1, src);
    float cv = __shfl_sync(0xffffffffu, e2, src);
    float sc0 = ((lane < 31) ? a : b) * inv;    // class lane+1
    float sc1 = ((lane < 31) ? b : cv) * inv;   // class lane+33
    float sc2 = cv * inv;                        // class lane+65 (lane<16)

    float4 p = ((const float4*)props)[img * NNROWS + row];
    float w  = p.z - p.x;
    float h  = p.w - p.y;
    float wh = w * h;
    const float4* D4 = (const float4*)(bbox + ((size_t)img * NNROWS + row) * ((CC + 1) * 4) + 4);
    unsigned* O = &g_ord[img][row * CC];

    int invc = 0;
#pragma unroll
    for (int k = 0; k < 3; k++) {
        int c = lane + 32 * k;
        if (c >= CC) break;
        float sc = (k == 0) ? sc0 : (k == 1) ? sc1 : sc2;
        bool valid = false;
        if (sc > 0.01f) {
            float4 d = D4[c];
            float dw = fminf(d.z / 5.0f, CLIPF);
            float dh = fminf(d.w / 5.0f, CLIPF);
            float area = __expf(dw + dh) * wh;
            valid = (area > 0.1f);
        }
        unsigned ordv;
        if (valid) {
            ordv = f2ord(sc);
            atomicAdd(&g_hist16[img][ordv >> 16], 1u);
        } else {
            ordv = (INVBIN << 16) | 0xFFFFu;   // f2ord(-1.0f)
            invc++;
        }
        O[c] = ordv;
    }
#pragma unroll
    for (int o = 16; o > 0; o >>= 1) invc += __shfl_xor_sync(0xffffffffu, invc, o);
    if (lane == 0 && invc) atomicAdd(&g_hist16[img][INVBIN], (unsigned)invc);
}

// ---------------- mega: select16 + compact + refine + sort + decode + NMS + out
__global__ __launch_bounds__(1024) void k_mega(const float* __restrict__ bbox,
                                               const float* __restrict__ props,
                                               float* __restrict__ out) {
    int img = blockIdx.x;
    int tid = threadIdx.x;
    int wid = tid >> 5;
    int lane = tid & 31;

    extern __shared__ ull dyn[];
    ull*    s_top    = dyn;                         // 2048 (complemented keys)
    ull*    s_cand   = dyn + KPRE;                  // CAPS
    float4* s_nmsb   = (float4*)(s_cand + CAPS);    // 2048
    float4* s_boxes  = s_nmsb + KPRE;               // 2048
    float*  s_scores = (float*)(s_boxes + KPRE);    // 2048
    int*    s_labels = (int*)(s_scores + KPRE);     // 2048

    __shared__ unsigned csum[256];
    __shared__ unsigned sb[256];
    __shared__ unsigned scan[256];
    __shared__ unsigned rhist[256];
    __shared__ int  s_dig;
    __shared__ unsigned s_acc;
    __shared__ unsigned s_prefix;
    __shared__ int s_cntA, s_cntC, s_cnt2, s_V, s_k2, snk;
    __shared__ ull s_pfx;
    __shared__ float4 kb[DETN];
    __shared__ int ki[DETN];
    __shared__ ull keepm[NWORDS];
    __shared__ int sdet[DETN];
    __shared__ int sflag[DETN];

    if (tid == 0) { s_cntA = 0; s_cntC = 0; s_cnt2 = 0; }

    // ---- phase 1: 16-bit bucket select ----
    for (int c = wid; c < 256; c += 32) {
        const unsigned* h = &g_hist16[img][c * 256];
        unsigned s = 0;
#pragma unroll
        for (int k = 0; k < 8; k++) s += h[lane + 32 * k];
#pragma unroll
        for (int o = 16; o > 0; o >>= 1) s += __shfl_xor_sync(0xffffffffu, s, o);
        if (lane == 0) csum[c] = s;
    }
    __syncthreads();
    sel_digit(csum, KPRE, scan, &s_dig, &s_acc, tid);
    int tc = s_dig;
    unsigned acc1 = s_acc;
    if (tid < 256) sb[tid] = g_hist16[img][tc * 256 + tid];
    __syncthreads();
    sel_digit(sb, KPRE - acc1, scan, &s_dig, &s_acc, tid);
    if (tid == 0) s_prefix = (unsigned)(tc * 256 + s_dig);
    __syncthreads();
    unsigned prefix = s_prefix;

    // re-zero this image's hist slice for the next replay (idempotent graph)
    {
        uint4* hz = (uint4*)g_hist16[img];
#pragma unroll
        for (int k = 0; k < 16; k++) hz[tid + 1024 * k] = make_uint4(0u, 0u, 0u, 0u);
    }

    // ---- phase 2: compact (>bucket -> s_top complemented, ==bucket -> s_cand) ----
    {
        const uint4* src = (const uint4*)g_ord[img];
        const int n4 = NC / 4;                    // 80000
        for (int it = 0; it < 79; it++) {
            int i = it * 1024 + tid;
            uint4 v = make_uint4(0u, 0u, 0u, 0u);
            if (i < n4) v = src[i];
#pragma unroll
            for (int e = 0; e < 4; e++) {
                unsigned ordv = (e == 0) ? v.x : (e == 1) ? v.y : (e == 2) ? v.z : v.w;
                unsigned p16 = ordv >> 16;
                bool ab = (p16 > prefix);
                bool eq = (p16 == prefix);
                unsigned balA = __ballot_sync(0xffffffffu, ab);
                unsigned balE = __ballot_sync(0xffffffffu, eq);
                int baseA = 0, baseE = 0;
                if (lane == 0) {
                    if (balA) baseA = atomicAdd(&s_cntA, __popc(balA));
                    if (balE) baseE = atomicAdd(&s_cntC, __popc(balE));
                }
                baseA = __shfl_sync(0xffffffffu, baseA, 0);
                baseE = __shfl_sync(0xffffffffu, baseE, 0);
                unsigned lm = (1u << lane) - 1u;
                unsigned idx = (unsigned)(i * 4 + e);
                ull key = ((ull)ordv << 32) | (ull)(0xFFFFFFFFu - idx);
                if (ab) {
                    s_top[baseA + __popc(balA & lm)] = ~key;
                } else if (eq) {
                    int p = baseE + __popc(balE & lm);
                    if (p < CAPS) s_cand[p] = key;
                }
            }
        }
    }
    __syncthreads();

    // ---- phase 3: exact 64-bit refine within pivot bucket ----
    int n = s_cntC; if (n > CAPS) n = CAPS;
    int above = s_cntA;
    if (tid == 0) { s_pfx = (ull)prefix << 48; s_k2 = KPRE - above; }
    __syncthreads();

    for (int r = 0; r < 6; r++) {
        int sh = 40 - 8 * r;
        if (tid < 256) rhist[tid] = 0;
        __syncthreads();
        ull hi_mask = ~((1ull << (sh + 8)) - 1ull);
        ull pfx = s_pfx;
        for (int i = tid; i < n; i += 1024) {
            ull key = s_cand[i];
            if ((key & hi_mask) == pfx)
                atomicAdd(&rhist[(unsigned)(key >> sh) & 0xFFu], 1u);
        }
        __syncthreads();
        sel_digit(rhist, (unsigned)s_k2, scan, &s_dig, &s_acc, tid);
        if (tid == 0) {
            s_pfx |= ((ull)s_dig) << sh;
            s_k2 -= (int)s_acc;
        }
        __syncthreads();
    }
    {
        ull pivot = s_pfx;
        for (int i = tid; i < n; i += 1024) {
            ull key = s_cand[i];
            if (key >= pivot) {
                int p = above + atomicAdd(&s_cnt2, 1);
                s_top[p] = ~key;
            }
        }
    }
    __syncthreads();

    // ---- phase 4: bitonic sort 2048 complemented keys ascending (= real desc) ----
    for (int ksz = 2; ksz <= KPRE; ksz <<= 1) {
        for (int j = ksz >> 1; j > 0; j >>= 1) {
            for (int i = tid; i < KPRE; i += 1024) {
                int ixj = i ^ j;
                if (ixj > i) {
                    ull a = s_top[i], b = s_top[ixj];
                    bool up = ((i & ksz) == 0);
                    if ((a > b) == up) { s_top[i] = b; s_top[ixj] = a; }
                }
            }
            __syncthreads();
        }
    }

    // ---- phase 5: decode top 2048 (precise expf) ----
    for (int i = tid; i < KPRE; i += 1024) {
        ull key = ~s_top[i];
        float sc = ord2f((unsigned)(key >> 32));
        unsigned idx = 0xFFFFFFFFu - (unsigned)(key & 0xFFFFFFFFull);
        int nr = (int)(idx / CC);
        int c  = (int)(idx - (unsigned)nr * CC);
        float4 p = ((const float4*)props)[img * NNROWS + nr];
        const float4* D4 = (const float4*)(bbox + ((size_t)img * NNROWS + nr) * ((CC + 1) * 4) + 4);
        float4 d = D4[c];
        float x1, y1, x2, y2;
        decode_box(d.x, d.y, d.z, d.w, p, x1, y1, x2, y2);
        s_scores[i] = sc;
        s_boxes[i]  = make_float4(x1, y1, x2, y2);
        float off = (float)(c + 1) * 4096.0f;
        s_nmsb[i]   = make_float4(x1 + off, y1 + off, x2 + off, y2 + off);
        s_labels[i] = c + 1;

        if (i == 0 && !(sc > 0.0f)) s_V = 0;
        if (sc > 0.0f) {
            if (i == KPRE - 1) s_V = KPRE;
            else {
                float nx = ord2f((unsigned)((~s_top[i + 1]) >> 32));
                if (!(nx > 0.0f)) s_V = i + 1;
            }
        }
    }
    __syncthreads();

    // ---- phase 6: lazy greedy NMS (warp 0), early exit at DETN keeps ----
    if (tid < 32) {
        if (lane < NWORDS) keepm[lane] = 0ull;
        int V = s_V;
        __syncwarp();
        int nk = 0;
        for (int i = 0; i < V && nk < DETN; i++) {
            float4 a = s_nmsb[i];
            float aw = fmaxf(a.z - a.x, 0.0f), ah = fmaxf(a.w - a.y, 0.0f);
            float areaA = aw * ah;
            bool sup = false;
            for (int j = lane; j < nk; j += 32) {
                float4 b = kb[j];
                float bw = fmaxf(b.z - b.x, 0.0f), bh = fmaxf(b.w - b.y, 0.0f);
                float w = fmaxf(fminf(a.z, b.z) - fmaxf(a.x, b.x), 0.0f);
                float h = fmaxf(fminf(a.w, b.w) - fmaxf(a.y, b.y), 0.0f);
                float inter = w * h;
                float uni = areaA + bw * bh - inter;
                if (inter / fmaxf(uni, 1e-9f) > 0.5f) sup = true;
            }
            if (!__any_sync(0xffffffffu, sup)) {
                if (lane == 0) {
                    kb[nk] = a;
                    ki[nk] = i;
                    keepm[i >> 6] |= (1ull << (i & 63));
                }
                __syncwarp();
                nk++;
            }
        }
        if (lane == 0) snk = nk;
    }
    __syncthreads();

    if (tid == 0) {
        int c = 0, nk = snk;
        for (int q = 0; q < nk; q++) { sdet[c] = ki[q]; sflag[c] = 1; c++; }
        for (int i = 0; i < KPRE && c < DETN; i++)
            if (!((keepm[i >> 6] >> (i & 63)) & 1ull)) { sdet[c] = i; sflag[c] = 0; c++; }
    }
    __syncthreads();

    if (tid < DETN) {
        int i = sdet[tid];
        float4 b = s_boxes[i];
        int o = img * DETN + tid;
        out[o * 4 + 0] = b.x;
        out[o * 4 + 1] = b.y;
        out[o * 4 + 2] = b.z;
        out[o * 4 + 3] = b.w;
        out[BB * DETN * 4 + o] = sflag[tid] ? s_scores[i] : -1.0f;
        out[BB * DETN * 5 + o] = (float)s_labels[i];
    }
}

// ---------------- launch ----------------
extern "C" void kernel_launch(void* const* d_in, const int* in_sizes, int n_in,
                              void* d_out, int out_size) {
    const float* label = (const float*)d_in[0];
    const float* bbox  = (const float*)d_in[1];
    const float* props = (const float*)d_in[2];
    float* out = (float*)d_out;

    const int MEGA_SMEM = (KPRE + CAPS) * 8 + KPRE * 16 * 2 + KPRE * 4 * 2; // 147456
    cudaFuncSetAttribute(k_mega, cudaFuncAttributeMaxDynamicSharedMemorySize, MEGA_SMEM);

    k_scorekey<<<dim3(500, BB), 256>>>(label, bbox, props);
    k_mega<<<BB, 1024, MEGA_SMEM>>>(bbox, props, out);
}